// round 16
// baseline (speedup 1.0000x reference)
#include <cuda_runtime.h>
#include <cuda_fp16.h>
#include <cstdint>

#define NMAX 100000
#define EMAX 3200000
#define F 128
#define FP8_SCALE 16.0f

typedef unsigned short h16_t;   // f16 storage

// Scratch (device globals — no allocation allowed)
__device__ int     g_cnt   [NMAX];
__device__ int     g_start [NMAX + 1];
__device__ int     g_cursor[NMAX];
__device__ int     g_bsum  [256];
__device__ int     g_boff  [256];
__device__ int     g_srow  [EMAX];              // edge row-ids sorted by col
__device__ float   g_dinv  [NMAX];
__device__ uint8_t g_h8    [(size_t)NMAX * F];  // GEMM out (both layers): fp8, prescaled dinv*16
__device__ uint8_t g_a8    [(size_t)NMAX * F];  // layer-1 agg output: fp8, relu'd, *16
__device__ h16_t   g_w1h   [F * F];             // W1 pre-converted to f16
__device__ h16_t   g_w2h   [F * F];             // W2 pre-converted to f16

// ---------------------------------------------------------------------------
// numeric helpers
// ---------------------------------------------------------------------------
__device__ __forceinline__ uint16_t f2_to_e4m3x2(float lo, float hi) {
    uint16_t r;
    asm("cvt.rn.satfinite.e4m3x2.f32 %0, %1, %2;" : "=h"(r) : "f"(hi), "f"(lo));
    return r;
}

__device__ __forceinline__ uint32_t e4m3x2_to_f16x2(uint16_t v) {
    uint32_t r;
    asm("cvt.rn.f16x2.e4m3x2 %0, %1;" : "=r"(r) : "h"(v));
    return r;
}

__device__ __forceinline__ void fp8x4_to_f16x2(uint32_t u, uint32_t& p0, uint32_t& p1) {
    p0 = e4m3x2_to_f16x2((uint16_t)(u & 0xFFFFu));
    p1 = e4m3x2_to_f16x2((uint16_t)(u >> 16));
}

__device__ __forceinline__ void fp8x4_to_h2(uint32_t u, __half2& p0, __half2& p1) {
    uint32_t r0, r1;
    fp8x4_to_f16x2(u, r0, r1);
    p0 = *(__half2*)&r0;
    p1 = *(__half2*)&r1;
}

__device__ __forceinline__ uint32_t pack_h2(__half2 h) { return *(uint32_t*)&h; }

// ---------------------------------------------------------------------------
// W pre-conversion: fp32 -> f16 (both weight matrices, one tiny kernel)
// ---------------------------------------------------------------------------
__global__ void k_convw(const float* __restrict__ W1, const float* __restrict__ W2,
                        h16_t* __restrict__ w1h, h16_t* __restrict__ w2h) {
    int i = blockIdx.x * blockDim.x + threadIdx.x;   // 0..4095 (float4 index)
    if (i >= (F * F) / 4) return;
    float4 v = __ldg((const float4*)W1 + i);
    uint2 u;
    u.x = pack_h2(__floats2half2_rn(v.x, v.y));
    u.y = pack_h2(__floats2half2_rn(v.z, v.w));
    ((uint2*)w1h)[i] = u;
    v = __ldg((const float4*)W2 + i);
    u.x = pack_h2(__floats2half2_rn(v.x, v.y));
    u.y = pack_h2(__floats2half2_rn(v.z, v.w));
    ((uint2*)w2h)[i] = u;
}

// ---------------------------------------------------------------------------
// degree histogram / dinv
// ---------------------------------------------------------------------------
__global__ void k_hist(const int* __restrict__ col, int* __restrict__ cnt, int E) {
    int i = blockIdx.x * blockDim.x + threadIdx.x;
    if (i < E) atomicAdd(&cnt[col[i]], 1);
}

__global__ void k_dinv(const int* __restrict__ cnt, float* __restrict__ dinv, int n) {
    int i = blockIdx.x * blockDim.x + threadIdx.x;
    if (i < n) dinv[i] = rsqrtf((float)(cnt[i] + 1));  // +1 self-loop
}

// ---------------------------------------------------------------------------
// Counting sort of edges by col
// ---------------------------------------------------------------------------
#define SCAN_BLK 1024

__global__ void k_blocksum(const int* __restrict__ cnt, int* __restrict__ bsum, int n) {
    __shared__ int sm[256];
    int t = threadIdx.x, b = blockIdx.x;
    int base = b * SCAN_BLK;
    int s = 0;
    #pragma unroll
    for (int k = 0; k < 4; k++) {
        int i = base + t * 4 + k;
        if (i < n) s += cnt[i];
    }
    sm[t] = s; __syncthreads();
    for (int off = 128; off > 0; off >>= 1) {
        if (t < off) sm[t] += sm[t + off];
        __syncthreads();
    }
    if (t == 0) bsum[b] = sm[0];
}

__global__ void k_scanbsum(const int* __restrict__ bsum, int* __restrict__ boff,
                           int* __restrict__ start, int nb, int n) {
    __shared__ int sm[256];
    int t = threadIdx.x;
    int v = (t < nb) ? bsum[t] : 0;
    sm[t] = v; __syncthreads();
    #pragma unroll
    for (int off = 1; off < 256; off <<= 1) {
        int x = 0;
        if (t >= off) x = sm[t - off];
        __syncthreads();
        sm[t] += x;
        __syncthreads();
    }
    if (t < nb) boff[t] = sm[t] - v;
    if (t == 255) start[n] = sm[255];
}

__global__ void k_writestart(const int* __restrict__ cnt, const int* __restrict__ boff,
                             int* __restrict__ start, int* __restrict__ cursor, int n) {
    __shared__ int sm[256];
    int t = threadIdx.x, b = blockIdx.x;
    int base = b * SCAN_BLK + t * 4;
    int c[4]; int s = 0;
    #pragma unroll
    for (int k = 0; k < 4; k++) {
        c[k] = (base + k < n) ? cnt[base + k] : 0;
        s += c[k];
    }
    sm[t] = s; __syncthreads();
    #pragma unroll
    for (int off = 1; off < 256; off <<= 1) {
        int x = 0;
        if (t >= off) x = sm[t - off];
        __syncthreads();
        sm[t] += x;
        __syncthreads();
    }
    int excl = boff[b] + sm[t] - s;
    #pragma unroll
    for (int k = 0; k < 4; k++) {
        int i = base + k;
        if (i < n) { start[i] = excl; cursor[i] = excl; }
        excl += c[k];
    }
}

__global__ void k_scatter(const int* __restrict__ row, const int* __restrict__ col,
                          int* __restrict__ cursor, int* __restrict__ srow, int E) {
    int i = blockIdx.x * blockDim.x + threadIdx.x;
    if (i >= E) return;
    int c = col[i];
    int pos = atomicAdd(&cursor[c], 1);
    srow[pos] = row[i];
}

// ---------------------------------------------------------------------------
// Tensor-core GEMM (f16 mma): H8(fp8) = (A @ Wh) * dinv[row] * esc
// Wh already f16. A fp32 (layer 1) or fp8 (layer 2, carries x16, esc=1).
// CTA = 128x128 tile, 512 threads (16 warps, warp tile 32x32).
// ---------------------------------------------------------------------------
#define SLD 136

__device__ __forceinline__ uint32_t smem_u32(const void* p) {
    return (uint32_t)__cvta_generic_to_shared(p);
}

__device__ __forceinline__ void ldsm_x4(uint32_t* r, uint32_t addr) {
    asm volatile("ldmatrix.sync.aligned.m8n8.x4.shared.b16 {%0,%1,%2,%3}, [%4];"
                 : "=r"(r[0]), "=r"(r[1]), "=r"(r[2]), "=r"(r[3]) : "r"(addr));
}

__device__ __forceinline__ void ldsm_x4_t(uint32_t* r, uint32_t addr) {
    asm volatile("ldmatrix.sync.aligned.m8n8.x4.trans.shared.b16 {%0,%1,%2,%3}, [%4];"
                 : "=r"(r[0]), "=r"(r[1]), "=r"(r[2]), "=r"(r[3]) : "r"(addr));
}

__device__ __forceinline__ void mma_f16(float* c, const uint32_t* a,
                                        uint32_t b0, uint32_t b1) {
    asm volatile(
        "mma.sync.aligned.m16n8k16.row.col.f32.f16.f16.f32 "
        "{%0,%1,%2,%3}, {%4,%5,%6,%7}, {%8,%9}, {%0,%1,%2,%3};"
        : "+f"(c[0]), "+f"(c[1]), "+f"(c[2]), "+f"(c[3])
        : "r"(a[0]), "r"(a[1]), "r"(a[2]), "r"(a[3]), "r"(b0), "r"(b1));
}

// A loads (streaming: read-once)
__device__ __forceinline__ uint2 load_a4(const float* base, int c4) {
    float4 v = __ldcs((const float4*)base + c4);
    uint2 u;
    u.x = pack_h2(__floats2half2_rn(v.x, v.y));
    u.y = pack_h2(__floats2half2_rn(v.z, v.w));
    return u;
}

__device__ __forceinline__ uint2 load_a4(const uint8_t* base, int c4) {
    uint32_t u = __ldcs((const uint32_t*)base + c4);
    uint2 r;
    fp8x4_to_f16x2(u, r.x, r.y);
    return r;
}

template <typename T>
__global__ void __launch_bounds__(512, 2)
k_gemm_mma(const T* __restrict__ A, const h16_t* __restrict__ Wh,
           const float* __restrict__ dinv, uint8_t* __restrict__ H8,
           float esc, int M) {
    extern __shared__ h16_t smh[];
    h16_t* As = smh;              // 128 x SLD
    h16_t* Ws = smh + 128 * SLD;  // 128 x SLD

    const int tid = threadIdx.x;
    const int block_row = blockIdx.x * 128;

    #pragma unroll
    for (int i = tid; i < 4096; i += 512) {
        int r = i >> 5, c4 = i & 31;
        *(uint2*)(Ws + r * SLD + c4 * 4) = __ldg((const uint2*)Wh + i);
    }
    #pragma unroll
    for (int i = tid; i < 4096; i += 512) {
        int r = i >> 5, c4 = i & 31;
        int gr = block_row + r;
        uint2 u = make_uint2(0u, 0u);
        if (gr < M) u = load_a4(A + (size_t)gr * F, c4);
        *(uint2*)(As + r * SLD + c4 * 4) = u;
    }
    __syncthreads();

    const int wid = tid >> 5, lane = tid & 31;
    const int wm = (wid & 3) * 32;
    const int wn = (wid >> 2) * 32;

    float acc[2][4][4];
    #pragma unroll
    for (int mt = 0; mt < 2; mt++)
        #pragma unroll
        for (int nt = 0; nt < 4; nt++)
            #pragma unroll
            for (int q = 0; q < 4; q++) acc[mt][nt][q] = 0.f;

    const uint32_t As_b = smem_u32(As);
    const uint32_t Ws_b = smem_u32(Ws);
    const int lrow = lane & 15;
    const int lcol = (lane >> 4) * 8;

    #pragma unroll
    for (int kb = 0; kb < 8; kb++) {
        uint32_t a[2][4];
        #pragma unroll
        for (int mt = 0; mt < 2; mt++) {
            int row = wm + mt * 16 + lrow;
            int col = kb * 16 + lcol;
            ldsm_x4(a[mt], As_b + (row * SLD + col) * 2);
        }
        uint32_t b[4][2];
        #pragma unroll
        for (int np = 0; np < 2; np++) {
            int krow = kb * 16 + lrow;
            int ncol = wn + np * 16 + lcol;
            uint32_t r[4];
            ldsm_x4_t(r, Ws_b + (krow * SLD + ncol) * 2);
            b[np * 2][0] = r[0]; b[np * 2][1] = r[1];
            b[np * 2 + 1][0] = r[2]; b[np * 2 + 1][1] = r[3];
        }
        #pragma unroll
        for (int mt = 0; mt < 2; mt++)
            #pragma unroll
            for (int nt = 0; nt < 4; nt++)
                mma_f16(acc[mt][nt], a[mt], b[nt][0], b[nt][1]);
    }

    #pragma unroll
    for (int mt = 0; mt < 2; mt++) {
        int r0 = block_row + wm + mt * 16 + (lane >> 2);
        int r1 = r0 + 8;
        float d0 = __ldg(dinv + min(r0, M - 1)) * esc;
        float d1 = __ldg(dinv + min(r1, M - 1)) * esc;
        #pragma unroll
        for (int nt = 0; nt < 4; nt++) {
            int col = wn + nt * 8 + (lane & 3) * 2;
            if (r0 < M)
                *(uint16_t*)(H8 + (size_t)r0 * F + col) =
                    f2_to_e4m3x2(acc[mt][nt][0] * d0, acc[mt][nt][1] * d0);
            if (r1 < M)
                *(uint16_t*)(H8 + (size_t)r1 * F + col) =
                    f2_to_e4m3x2(acc[mt][nt][2] * d1, acc[mt][nt][3] * d1);
        }
    }
}

// ---------------------------------------------------------------------------
// Gather aggregation over prescaled fp8 H' (128B rows)  [round-13 form]:
//   a[c] = (dc/16) * ( sum_{r in N(c)} H'[r] + H'[c] ) + bias
// Warp handles 4 nodes; lane = 4 features (4B load); 8 row-loads in flight.
// ---------------------------------------------------------------------------
#define NPW 4

__device__ __forceinline__ void tree4_acc(uint32_t u0, uint32_t u1,
                                          uint32_t u2, uint32_t u3, float4& acc) {
    __half2 a0, b0, a1, b1, a2, b2, a3, b3;
    fp8x4_to_h2(u0, a0, b0);
    fp8x4_to_h2(u1, a1, b1);
    fp8x4_to_h2(u2, a2, b2);
    fp8x4_to_h2(u3, a3, b3);
    __half2 sa = __hadd2(__hadd2(a0, a1), __hadd2(a2, a3));
    __half2 sb = __hadd2(__hadd2(b0, b1), __hadd2(b2, b3));
    float2 fa = __half22float2(sa), fb = __half22float2(sb);
    acc.x += fa.x; acc.y += fa.y; acc.z += fb.x; acc.w += fb.y;
}

template <bool FUSE_HEAD>
__global__ void __launch_bounds__(256)
k_agg(const int* __restrict__ start, const int* __restrict__ srow,
      const float* __restrict__ dinv, const uint8_t* __restrict__ H8,
      const float* __restrict__ bias,
      const float* __restrict__ Wl, const float* __restrict__ bl,
      uint8_t* __restrict__ hout8, float* __restrict__ fout, int n) {
    const int lane = threadIdx.x & 31;
    const int warp = (blockIdx.x * blockDim.x + threadIdx.x) >> 5;
    int c0 = warp * NPW;
    if (c0 >= n) return;
    int c_end = min(c0 + NPW, n);

    float4 bv = __ldg((const float4*)bias + lane);
    float4 wv = make_float4(0.f, 0.f, 0.f, 0.f);
    float blv = 0.f;
    if (FUSE_HEAD) { wv = __ldg((const float4*)Wl + lane); blv = __ldg(bl); }

    for (int c = c0; c < c_end; c++) {
        int beg = __ldg(start + c);
        int end = __ldg(start + c + 1);
        float dc = __ldg(dinv + c) * (1.0f / FP8_SCALE);

        uint32_t su = __ldg((const uint32_t*)(H8 + (size_t)c * F) + lane);
        __half2 spa, spb; fp8x4_to_h2(su, spa, spb);
        float2 sfa = __half22float2(spa), sfb = __half22float2(spb);
        float4 acc = make_float4(sfa.x, sfa.y, sfb.x, sfb.y);

        for (int i = beg; i < end; i += 32) {
            int idx = i + lane;
            int rr = __ldcs(srow + (idx < end ? idx : end - 1));
            int cnt = min(end - i, 32);
            int j = 0;
            for (; j + 8 <= cnt; j += 8) {
                int r0 = __shfl_sync(0xFFFFFFFFu, rr, j);
                int r1 = __shfl_sync(0xFFFFFFFFu, rr, j + 1);
                int r2 = __shfl_sync(0xFFFFFFFFu, rr, j + 2);
                int r3 = __shfl_sync(0xFFFFFFFFu, rr, j + 3);
                int r4 = __shfl_sync(0xFFFFFFFFu, rr, j + 4);
                int r5 = __shfl_sync(0xFFFFFFFFu, rr, j + 5);
                int r6 = __shfl_sync(0xFFFFFFFFu, rr, j + 6);
                int r7 = __shfl_sync(0xFFFFFFFFu, rr, j + 7);
                uint32_t u0 = __ldg((const uint32_t*)(H8 + (size_t)r0 * F) + lane);
                uint32_t u1 = __ldg((const uint32_t*)(H8 + (size_t)r1 * F) + lane);
                uint32_t u2 = __ldg((const uint32_t*)(H8 + (size_t)r2 * F) + lane);
                uint32_t u3 = __ldg((const uint32_t*)(H8 + (size_t)r3 * F) + lane);
                uint32_t u4 = __ldg((const uint32_t*)(H8 + (size_t)r4 * F) + lane);
                uint32_t u5 = __ldg((const uint32_t*)(H8 + (size_t)r5 * F) + lane);
                uint32_t u6 = __ldg((const uint32_t*)(H8 + (size_t)r6 * F) + lane);
                uint32_t u7 = __ldg((const uint32_t*)(H8 + (size_t)r7 * F) + lane);
                tree4_acc(u0, u1, u2, u3, acc);
                tree4_acc(u4, u5, u6, u7, acc);
            }
            for (; j + 4 <= cnt; j += 4) {
                int r0 = __shfl_sync(0xFFFFFFFFu, rr, j);
                int r1 = __shfl_sync(0xFFFFFFFFu, rr, j + 1);
                int r2 = __shfl_sync(0xFFFFFFFFu, rr, j + 2);
                int r3 = __shfl_sync(0xFFFFFFFFu, rr, j + 3);
                uint32_t u0 = __ldg((const uint32_t*)(H8 + (size_t)r0 * F) + lane);
                uint32_t u1 = __ldg((const uint32_t*)(H8 + (size_t)r1 * F) + lane);
                uint32_t u2 = __ldg((const uint32_t*)(H8 + (size_t)r2 * F) + lane);
                uint32_t u3 = __ldg((const uint32_t*)(H8 + (size_t)r3 * F) + lane);
                tree4_acc(u0, u1, u2, u3, acc);
            }
            for (; j < cnt; j++) {
                int r0 = __shfl_sync(0xFFFFFFFFu, rr, j);
                uint32_t u0 = __ldg((const uint32_t*)(H8 + (size_t)r0 * F) + lane);
                __half2 pa, pb; fp8x4_to_h2(u0, pa, pb);
                float2 fa = __half22float2(pa), fb = __half22float2(pb);
                acc.x += fa.x; acc.y += fa.y; acc.z += fb.x; acc.w += fb.y;
            }
        }

        float4 o = make_float4(fmaf(dc, acc.x, bv.x), fmaf(dc, acc.y, bv.y),
                               fmaf(dc, acc.z, bv.z), fmaf(dc, acc.w, bv.w));

        if (!FUSE_HEAD) {
            o.x = fmaxf(o.x, 0.f) * FP8_SCALE; o.y = fmaxf(o.y, 0.f) * FP8_SCALE;
            o.z = fmaxf(o.z, 0.f) * FP8_SCALE; o.w = fmaxf(o.w, 0.f) * FP8_SCALE;
            uint32_t lo = f2_to_e4m3x2(o.x, o.y);
            uint32_t hi = f2_to_e4m3x2(o.z, o.w);
            *((uint32_t*)(hout8 + (size_t)c * F) + lane) = lo | (hi << 16);
        } else {
            float s = fmaxf(o.x, 0.f) * wv.x + fmaxf(o.y, 0.f) * wv.y +
                      fmaxf(o.z, 0.f) * wv.z + fmaxf(o.w, 0.f) * wv.w;
            #pragma unroll
            for (int off = 16; off; off >>= 1) s += __shfl_xor_sync(0xFFFFFFFFu, s, off);
            if (lane == 0) {
                float z = s + blv;
                fout[c] = 1.0f / (1.0f + expf(-z));
            }
        }
    }
}

// ---------------------------------------------------------------------------
extern "C" void kernel_launch(void* const* d_in, const int* in_sizes, int n_in,
                              void* d_out, int out_size) {
    const float* x  = (const float*)d_in[0];
    const int*   ei = (const int*)  d_in[1];
    const float* W1 = (const float*)d_in[2];
    const float* b1 = (const float*)d_in[3];
    const float* W2 = (const float*)d_in[4];
    const float* b2 = (const float*)d_in[5];
    const float* Wl = (const float*)d_in[6];
    const float* bl = (const float*)d_in[7];

    int n = in_sizes[0] / F;
    int E = in_sizes[1] / 2;
    const int* rowp = ei;
    const int* colp = ei + E;

    int *cnt, *start, *cursor, *bsum, *boff, *srow;
    float *dinv;
    uint8_t *h8, *a8;
    h16_t *w1h, *w2h;
    cudaGetSymbolAddress((void**)&cnt,    g_cnt);
    cudaGetSymbolAddress((void**)&start,  g_start);
    cudaGetSymbolAddress((void**)&cursor, g_cursor);
    cudaGetSymbolAddress((void**)&bsum,   g_bsum);
    cudaGetSymbolAddress((void**)&boff,   g_boff);
    cudaGetSymbolAddress((void**)&srow,   g_srow);
    cudaGetSymbolAddress((void**)&dinv,   g_dinv);
    cudaGetSymbolAddress((void**)&h8,     g_h8);
    cudaGetSymbolAddress((void**)&a8,     g_a8);
    cudaGetSymbolAddress((void**)&w1h,    g_w1h);
    cudaGetSymbolAddress((void**)&w2h,    g_w2h);

    const size_t gemm_smem = (size_t)(2 * 128 * SLD) * sizeof(h16_t);
    cudaFuncSetAttribute((const void*)k_gemm_mma<float>,
                         cudaFuncAttributeMaxDynamicSharedMemorySize, (int)gemm_smem);
    cudaFuncSetAttribute((const void*)k_gemm_mma<uint8_t>,
                         cudaFuncAttributeMaxDynamicSharedMemorySize, (int)gemm_smem);

    // Side stream + events for overlapping prep with GEMM1.
    static cudaStream_t s2 = nullptr;
    static cudaEvent_t evF = nullptr, evB = nullptr, evW = nullptr;
    static int init_tried = 0;
    if (!init_tried) {
        init_tried = 1;
        if (cudaStreamCreateWithFlags(&s2, cudaStreamNonBlocking) != cudaSuccess) s2 = nullptr;
        if (cudaEventCreateWithFlags(&evF, cudaEventDisableTiming) != cudaSuccess) evF = nullptr;
        if (cudaEventCreateWithFlags(&evB, cudaEventDisableTiming) != cudaSuccess) evB = nullptr;
        if (cudaEventCreateWithFlags(&evW, cudaEventDisableTiming) != cudaSuccess) evW = nullptr;
    }
    bool par = (s2 != nullptr) && (evF != nullptr) && (evB != nullptr) && (evW != nullptr);

    int nb = (n + SCAN_BLK - 1) / SCAN_BLK;
    int gemm_grid = (n + 127) / 128;
    int agg_grid  = ((n + NPW - 1) / NPW * 32 + 255) / 256;

    cudaMemsetAsync(cnt, 0, (size_t)n * sizeof(int), 0);

    if (par) {
        // stream 0: degree + dinv  (also the capture-fork origin)
        k_hist<<<(E + 255) / 256, 256>>>(colp, cnt, E);
        k_dinv<<<(n + 255) / 256, 256>>>(cnt, dinv, n);
        cudaEventRecord(evF, 0);                    // fork point: cnt+dinv done
        // s2: forked from stream 0 (capture-legal), runs convw + sort chain
        cudaStreamWaitEvent(s2, evF, 0);
        k_convw<<<16, 256, 0, s2>>>(W1, W2, w1h, w2h);
        cudaEventRecord(evW, s2);
        // stream 0: GEMM1 (needs dinv + w1h)
        cudaStreamWaitEvent(0, evW, 0);
        k_gemm_mma<float><<<gemm_grid, 512, gemm_smem>>>(x, w1h, dinv, h8, FP8_SCALE, n); // 4th launch (profiled)
        // s2: sort chain (needs cnt; ordered after evF on s2)
        k_blocksum  <<<nb, 256, 0, s2>>>(cnt, bsum, n);
        k_scanbsum  <<<1, 256, 0, s2>>>(bsum, boff, start, nb, n);
        k_writestart<<<nb, 256, 0, s2>>>(cnt, boff, start, cursor, n);
        k_scatter   <<<(E + 255) / 256, 256, 0, s2>>>(rowp, colp, cursor, srow, E);
        cudaEventRecord(evB, s2);
        cudaStreamWaitEvent(0, evB, 0);
    } else {
        k_hist<<<(E + 255) / 256, 256>>>(colp, cnt, E);
        k_dinv<<<(n + 255) / 256, 256>>>(cnt, dinv, n);
        k_convw<<<16, 256>>>(W1, W2, w1h, w2h);
        k_gemm_mma<float><<<gemm_grid, 512, gemm_smem>>>(x, w1h, dinv, h8, FP8_SCALE, n);
        k_blocksum  <<<nb, 256>>>(cnt, bsum, n);
        k_scanbsum  <<<1, 256>>>(bsum, boff, start, nb, n);
        k_writestart<<<nb, 256>>>(cnt, boff, start, cursor, n);
        k_scatter   <<<(E + 255) / 256, 256>>>(rowp, colp, cursor, srow, E);
    }

    // --- layer 1 agg (fp8 gather) -> fp8 a8 (x16) ---
    k_agg<false><<<agg_grid, 256>>>(start, srow, dinv, h8, b1, nullptr, nullptr, a8, nullptr, n);

    // --- layer 2: A carries x16 -> esc = 1.0 keeps H8 = 16*dinv*(a@W2) ---
    k_gemm_mma<uint8_t><<<gemm_grid, 512, gemm_smem>>>(a8, w2h, dinv, h8, 1.0f, n);
    k_agg<true><<<agg_grid, 256>>>(start, srow, dinv, h8, b2, Wl, bl, nullptr, (float*)d_out, n);
}

// round 17
// speedup vs baseline: 1.0329x; 1.0329x over previous
#include <cuda_runtime.h>
#include <cuda_fp16.h>
#include <cstdint>

#define NMAX 100000
#define EMAX 3200000
#define F 128
#define FP8_SCALE 16.0f

typedef unsigned short h16_t;   // f16 storage

// Scratch (device globals — no allocation allowed)
__device__ int     g_cnt   [NMAX];
__device__ int     g_start [NMAX + 1];
__device__ int     g_cursor[NMAX];
__device__ int     g_bsum  [256];
__device__ int     g_boff  [256];
__device__ int     g_srow  [EMAX];              // edge row-ids sorted by col
__device__ float   g_dinv  [NMAX];
__device__ uint8_t g_h8    [(size_t)NMAX * F];  // GEMM out (both layers): fp8, prescaled dinv*16
__device__ uint8_t g_a8    [(size_t)NMAX * F];  // layer-1 agg output: fp8, relu'd, *16
__device__ h16_t   g_w1h   [F * F];             // W1 pre-converted to f16
__device__ h16_t   g_w2h   [F * F];             // W2 pre-converted to f16

// ---------------------------------------------------------------------------
// numeric helpers
// ---------------------------------------------------------------------------
__device__ __forceinline__ uint16_t f2_to_e4m3x2(float lo, float hi) {
    uint16_t r;
    asm("cvt.rn.satfinite.e4m3x2.f32 %0, %1, %2;" : "=h"(r) : "f"(hi), "f"(lo));
    return r;
}

__device__ __forceinline__ uint32_t e4m3x2_to_f16x2(uint16_t v) {
    uint32_t r;
    asm("cvt.rn.f16x2.e4m3x2 %0, %1;" : "=r"(r) : "h"(v));
    return r;
}

__device__ __forceinline__ void fp8x4_to_f16x2(uint32_t u, uint32_t& p0, uint32_t& p1) {
    p0 = e4m3x2_to_f16x2((uint16_t)(u & 0xFFFFu));
    p1 = e4m3x2_to_f16x2((uint16_t)(u >> 16));
}

__device__ __forceinline__ void fp8x4_to_h2(uint32_t u, __half2& p0, __half2& p1) {
    uint32_t r0, r1;
    fp8x4_to_f16x2(u, r0, r1);
    p0 = *(__half2*)&r0;
    p1 = *(__half2*)&r1;
}

__device__ __forceinline__ uint32_t pack_h2(__half2 h) { return *(uint32_t*)&h; }

// ---------------------------------------------------------------------------
// W pre-conversion: fp32 -> f16 (both weight matrices, one tiny kernel)
// ---------------------------------------------------------------------------
__global__ void k_convw(const float* __restrict__ W1, const float* __restrict__ W2,
                        h16_t* __restrict__ w1h, h16_t* __restrict__ w2h) {
    int i = blockIdx.x * blockDim.x + threadIdx.x;   // 0..4095 (float4 index)
    if (i >= (F * F) / 4) return;
    float4 v = __ldg((const float4*)W1 + i);
    uint2 u;
    u.x = pack_h2(__floats2half2_rn(v.x, v.y));
    u.y = pack_h2(__floats2half2_rn(v.z, v.w));
    ((uint2*)w1h)[i] = u;
    v = __ldg((const float4*)W2 + i);
    u.x = pack_h2(__floats2half2_rn(v.x, v.y));
    u.y = pack_h2(__floats2half2_rn(v.z, v.w));
    ((uint2*)w2h)[i] = u;
}

// ---------------------------------------------------------------------------
// degree histogram / dinv
// ---------------------------------------------------------------------------
__global__ void k_hist(const int* __restrict__ col, int* __restrict__ cnt, int E) {
    int i = blockIdx.x * blockDim.x + threadIdx.x;
    if (i < E) atomicAdd(&cnt[col[i]], 1);
}

__global__ void k_dinv(const int* __restrict__ cnt, float* __restrict__ dinv, int n) {
    int i = blockIdx.x * blockDim.x + threadIdx.x;
    if (i < n) dinv[i] = rsqrtf((float)(cnt[i] + 1));  // +1 self-loop
}

// ---------------------------------------------------------------------------
// Counting sort of edges by col
// ---------------------------------------------------------------------------
#define SCAN_BLK 1024

__global__ void k_blocksum(const int* __restrict__ cnt, int* __restrict__ bsum, int n) {
    __shared__ int sm[256];
    int t = threadIdx.x, b = blockIdx.x;
    int base = b * SCAN_BLK;
    int s = 0;
    #pragma unroll
    for (int k = 0; k < 4; k++) {
        int i = base + t * 4 + k;
        if (i < n) s += cnt[i];
    }
    sm[t] = s; __syncthreads();
    for (int off = 128; off > 0; off >>= 1) {
        if (t < off) sm[t] += sm[t + off];
        __syncthreads();
    }
    if (t == 0) bsum[b] = sm[0];
}

__global__ void k_scanbsum(const int* __restrict__ bsum, int* __restrict__ boff,
                           int* __restrict__ start, int nb, int n) {
    __shared__ int sm[256];
    int t = threadIdx.x;
    int v = (t < nb) ? bsum[t] : 0;
    sm[t] = v; __syncthreads();
    #pragma unroll
    for (int off = 1; off < 256; off <<= 1) {
        int x = 0;
        if (t >= off) x = sm[t - off];
        __syncthreads();
        sm[t] += x;
        __syncthreads();
    }
    if (t < nb) boff[t] = sm[t] - v;
    if (t == 255) start[n] = sm[255];
}

__global__ void k_writestart(const int* __restrict__ cnt, const int* __restrict__ boff,
                             int* __restrict__ start, int* __restrict__ cursor, int n) {
    __shared__ int sm[256];
    int t = threadIdx.x, b = blockIdx.x;
    int base = b * SCAN_BLK + t * 4;
    int c[4]; int s = 0;
    #pragma unroll
    for (int k = 0; k < 4; k++) {
        c[k] = (base + k < n) ? cnt[base + k] : 0;
        s += c[k];
    }
    sm[t] = s; __syncthreads();
    #pragma unroll
    for (int off = 1; off < 256; off <<= 1) {
        int x = 0;
        if (t >= off) x = sm[t - off];
        __syncthreads();
        sm[t] += x;
        __syncthreads();
    }
    int excl = boff[b] + sm[t] - s;
    #pragma unroll
    for (int k = 0; k < 4; k++) {
        int i = base + k;
        if (i < n) { start[i] = excl; cursor[i] = excl; }
        excl += c[k];
    }
}

__global__ void k_scatter(const int* __restrict__ row, const int* __restrict__ col,
                          int* __restrict__ cursor, int* __restrict__ srow, int E) {
    int i = blockIdx.x * blockDim.x + threadIdx.x;
    if (i >= E) return;
    int c = col[i];
    int pos = atomicAdd(&cursor[c], 1);
    srow[pos] = row[i];
}

// ---------------------------------------------------------------------------
// Tensor-core GEMM (f16 mma): H8(fp8) = (A @ Wh) * dinv[row] * esc
// Wh already f16. A fp32 (layer 1) or fp8 (layer 2, carries x16, esc=1).
// CTA = 128x128 tile, 512 threads (16 warps, warp tile 32x32).
// ---------------------------------------------------------------------------
#define SLD 136

__device__ __forceinline__ uint32_t smem_u32(const void* p) {
    return (uint32_t)__cvta_generic_to_shared(p);
}

__device__ __forceinline__ void ldsm_x4(uint32_t* r, uint32_t addr) {
    asm volatile("ldmatrix.sync.aligned.m8n8.x4.shared.b16 {%0,%1,%2,%3}, [%4];"
                 : "=r"(r[0]), "=r"(r[1]), "=r"(r[2]), "=r"(r[3]) : "r"(addr));
}

__device__ __forceinline__ void ldsm_x4_t(uint32_t* r, uint32_t addr) {
    asm volatile("ldmatrix.sync.aligned.m8n8.x4.trans.shared.b16 {%0,%1,%2,%3}, [%4];"
                 : "=r"(r[0]), "=r"(r[1]), "=r"(r[2]), "=r"(r[3]) : "r"(addr));
}

__device__ __forceinline__ void mma_f16(float* c, const uint32_t* a,
                                        uint32_t b0, uint32_t b1) {
    asm volatile(
        "mma.sync.aligned.m16n8k16.row.col.f32.f16.f16.f32 "
        "{%0,%1,%2,%3}, {%4,%5,%6,%7}, {%8,%9}, {%0,%1,%2,%3};"
        : "+f"(c[0]), "+f"(c[1]), "+f"(c[2]), "+f"(c[3])
        : "r"(a[0]), "r"(a[1]), "r"(a[2]), "r"(a[3]), "r"(b0), "r"(b1));
}

// A loads (streaming: read-once)
__device__ __forceinline__ uint2 load_a4(const float* base, int c4) {
    float4 v = __ldcs((const float4*)base + c4);
    uint2 u;
    u.x = pack_h2(__floats2half2_rn(v.x, v.y));
    u.y = pack_h2(__floats2half2_rn(v.z, v.w));
    return u;
}

__device__ __forceinline__ uint2 load_a4(const uint8_t* base, int c4) {
    uint32_t u = __ldcs((const uint32_t*)base + c4);
    uint2 r;
    fp8x4_to_f16x2(u, r.x, r.y);
    return r;
}

template <typename T>
__global__ void __launch_bounds__(512, 2)
k_gemm_mma(const T* __restrict__ A, const h16_t* __restrict__ Wh,
           const float* __restrict__ dinv, uint8_t* __restrict__ H8,
           float esc, int M) {
    extern __shared__ h16_t smh[];
    h16_t* As = smh;              // 128 x SLD
    h16_t* Ws = smh + 128 * SLD;  // 128 x SLD

    const int tid = threadIdx.x;
    const int block_row = blockIdx.x * 128;

    #pragma unroll
    for (int i = tid; i < 4096; i += 512) {
        int r = i >> 5, c4 = i & 31;
        *(uint2*)(Ws + r * SLD + c4 * 4) = __ldg((const uint2*)Wh + i);
    }
    #pragma unroll
    for (int i = tid; i < 4096; i += 512) {
        int r = i >> 5, c4 = i & 31;
        int gr = block_row + r;
        uint2 u = make_uint2(0u, 0u);
        if (gr < M) u = load_a4(A + (size_t)gr * F, c4);
        *(uint2*)(As + r * SLD + c4 * 4) = u;
    }
    __syncthreads();

    const int wid = tid >> 5, lane = tid & 31;
    const int wm = (wid & 3) * 32;
    const int wn = (wid >> 2) * 32;

    float acc[2][4][4];
    #pragma unroll
    for (int mt = 0; mt < 2; mt++)
        #pragma unroll
        for (int nt = 0; nt < 4; nt++)
            #pragma unroll
            for (int q = 0; q < 4; q++) acc[mt][nt][q] = 0.f;

    const uint32_t As_b = smem_u32(As);
    const uint32_t Ws_b = smem_u32(Ws);
    const int lrow = lane & 15;
    const int lcol = (lane >> 4) * 8;

    #pragma unroll
    for (int kb = 0; kb < 8; kb++) {
        uint32_t a[2][4];
        #pragma unroll
        for (int mt = 0; mt < 2; mt++) {
            int row = wm + mt * 16 + lrow;
            int col = kb * 16 + lcol;
            ldsm_x4(a[mt], As_b + (row * SLD + col) * 2);
        }
        uint32_t b[4][2];
        #pragma unroll
        for (int np = 0; np < 2; np++) {
            int krow = kb * 16 + lrow;
            int ncol = wn + np * 16 + lcol;
            uint32_t r[4];
            ldsm_x4_t(r, Ws_b + (krow * SLD + ncol) * 2);
            b[np * 2][0] = r[0]; b[np * 2][1] = r[1];
            b[np * 2 + 1][0] = r[2]; b[np * 2 + 1][1] = r[3];
        }
        #pragma unroll
        for (int mt = 0; mt < 2; mt++)
            #pragma unroll
            for (int nt = 0; nt < 4; nt++)
                mma_f16(acc[mt][nt], a[mt], b[nt][0], b[nt][1]);
    }

    #pragma unroll
    for (int mt = 0; mt < 2; mt++) {
        int r0 = block_row + wm + mt * 16 + (lane >> 2);
        int r1 = r0 + 8;
        float d0 = __ldg(dinv + min(r0, M - 1)) * esc;
        float d1 = __ldg(dinv + min(r1, M - 1)) * esc;
        #pragma unroll
        for (int nt = 0; nt < 4; nt++) {
            int col = wn + nt * 8 + (lane & 3) * 2;
            if (r0 < M)
                *(uint16_t*)(H8 + (size_t)r0 * F + col) =
                    f2_to_e4m3x2(acc[mt][nt][0] * d0, acc[mt][nt][1] * d0);
            if (r1 < M)
                *(uint16_t*)(H8 + (size_t)r1 * F + col) =
                    f2_to_e4m3x2(acc[mt][nt][2] * d1, acc[mt][nt][3] * d1);
        }
    }
}

// ---------------------------------------------------------------------------
// Gather aggregation over prescaled fp8 H' (128B rows)  [round-13 form]:
//   a[c] = (dc/16) * ( sum_{r in N(c)} H'[r] + H'[c] ) + bias
// Warp handles 4 nodes; lane = 4 features (4B load); 8 row-loads in flight.
// ---------------------------------------------------------------------------
#define NPW 4

__device__ __forceinline__ void tree4_acc(uint32_t u0, uint32_t u1,
                                          uint32_t u2, uint32_t u3, float4& acc) {
    __half2 a0, b0, a1, b1, a2, b2, a3, b3;
    fp8x4_to_h2(u0, a0, b0);
    fp8x4_to_h2(u1, a1, b1);
    fp8x4_to_h2(u2, a2, b2);
    fp8x4_to_h2(u3, a3, b3);
    __half2 sa = __hadd2(__hadd2(a0, a1), __hadd2(a2, a3));
    __half2 sb = __hadd2(__hadd2(b0, b1), __hadd2(b2, b3));
    float2 fa = __half22float2(sa), fb = __half22float2(sb);
    acc.x += fa.x; acc.y += fa.y; acc.z += fb.x; acc.w += fb.y;
}

template <bool FUSE_HEAD>
__global__ void __launch_bounds__(256)
k_agg(const int* __restrict__ start, const int* __restrict__ srow,
      const float* __restrict__ dinv, const uint8_t* __restrict__ H8,
      const float* __restrict__ bias,
      const float* __restrict__ Wl, const float* __restrict__ bl,
      uint8_t* __restrict__ hout8, float* __restrict__ fout, int n) {
    const int lane = threadIdx.x & 31;
    const int warp = (blockIdx.x * blockDim.x + threadIdx.x) >> 5;
    int c0 = warp * NPW;
    if (c0 >= n) return;
    int c_end = min(c0 + NPW, n);

    float4 bv = __ldg((const float4*)bias + lane);
    float4 wv = make_float4(0.f, 0.f, 0.f, 0.f);
    float blv = 0.f;
    if (FUSE_HEAD) { wv = __ldg((const float4*)Wl + lane); blv = __ldg(bl); }

    for (int c = c0; c < c_end; c++) {
        int beg = __ldg(start + c);
        int end = __ldg(start + c + 1);
        float dc = __ldg(dinv + c) * (1.0f / FP8_SCALE);

        uint32_t su = __ldg((const uint32_t*)(H8 + (size_t)c * F) + lane);
        __half2 spa, spb; fp8x4_to_h2(su, spa, spb);
        float2 sfa = __half22float2(spa), sfb = __half22float2(spb);
        float4 acc = make_float4(sfa.x, sfa.y, sfb.x, sfb.y);

        for (int i = beg; i < end; i += 32) {
            int idx = i + lane;
            int rr = __ldcs(srow + (idx < end ? idx : end - 1));
            int cnt = min(end - i, 32);
            int j = 0;
            for (; j + 8 <= cnt; j += 8) {
                int r0 = __shfl_sync(0xFFFFFFFFu, rr, j);
                int r1 = __shfl_sync(0xFFFFFFFFu, rr, j + 1);
                int r2 = __shfl_sync(0xFFFFFFFFu, rr, j + 2);
                int r3 = __shfl_sync(0xFFFFFFFFu, rr, j + 3);
                int r4 = __shfl_sync(0xFFFFFFFFu, rr, j + 4);
                int r5 = __shfl_sync(0xFFFFFFFFu, rr, j + 5);
                int r6 = __shfl_sync(0xFFFFFFFFu, rr, j + 6);
                int r7 = __shfl_sync(0xFFFFFFFFu, rr, j + 7);
                uint32_t u0 = __ldg((const uint32_t*)(H8 + (size_t)r0 * F) + lane);
                uint32_t u1 = __ldg((const uint32_t*)(H8 + (size_t)r1 * F) + lane);
                uint32_t u2 = __ldg((const uint32_t*)(H8 + (size_t)r2 * F) + lane);
                uint32_t u3 = __ldg((const uint32_t*)(H8 + (size_t)r3 * F) + lane);
                uint32_t u4 = __ldg((const uint32_t*)(H8 + (size_t)r4 * F) + lane);
                uint32_t u5 = __ldg((const uint32_t*)(H8 + (size_t)r5 * F) + lane);
                uint32_t u6 = __ldg((const uint32_t*)(H8 + (size_t)r6 * F) + lane);
                uint32_t u7 = __ldg((const uint32_t*)(H8 + (size_t)r7 * F) + lane);
                tree4_acc(u0, u1, u2, u3, acc);
                tree4_acc(u4, u5, u6, u7, acc);
            }
            for (; j + 4 <= cnt; j += 4) {
                int r0 = __shfl_sync(0xFFFFFFFFu, rr, j);
                int r1 = __shfl_sync(0xFFFFFFFFu, rr, j + 1);
                int r2 = __shfl_sync(0xFFFFFFFFu, rr, j + 2);
                int r3 = __shfl_sync(0xFFFFFFFFu, rr, j + 3);
                uint32_t u0 = __ldg((const uint32_t*)(H8 + (size_t)r0 * F) + lane);
                uint32_t u1 = __ldg((const uint32_t*)(H8 + (size_t)r1 * F) + lane);
                uint32_t u2 = __ldg((const uint32_t*)(H8 + (size_t)r2 * F) + lane);
                uint32_t u3 = __ldg((const uint32_t*)(H8 + (size_t)r3 * F) + lane);
                tree4_acc(u0, u1, u2, u3, acc);
            }
            for (; j < cnt; j++) {
                int r0 = __shfl_sync(0xFFFFFFFFu, rr, j);
                uint32_t u0 = __ldg((const uint32_t*)(H8 + (size_t)r0 * F) + lane);
                __half2 pa, pb; fp8x4_to_h2(u0, pa, pb);
                float2 fa = __half22float2(pa), fb = __half22float2(pb);
                acc.x += fa.x; acc.y += fa.y; acc.z += fb.x; acc.w += fb.y;
            }
        }

        float4 o = make_float4(fmaf(dc, acc.x, bv.x), fmaf(dc, acc.y, bv.y),
                               fmaf(dc, acc.z, bv.z), fmaf(dc, acc.w, bv.w));

        if (!FUSE_HEAD) {
            o.x = fmaxf(o.x, 0.f) * FP8_SCALE; o.y = fmaxf(o.y, 0.f) * FP8_SCALE;
            o.z = fmaxf(o.z, 0.f) * FP8_SCALE; o.w = fmaxf(o.w, 0.f) * FP8_SCALE;
            uint32_t lo = f2_to_e4m3x2(o.x, o.y);
            uint32_t hi = f2_to_e4m3x2(o.z, o.w);
            *((uint32_t*)(hout8 + (size_t)c * F) + lane) = lo | (hi << 16);
        } else {
            float s = fmaxf(o.x, 0.f) * wv.x + fmaxf(o.y, 0.f) * wv.y +
                      fmaxf(o.z, 0.f) * wv.z + fmaxf(o.w, 0.f) * wv.w;
            #pragma unroll
            for (int off = 16; off; off >>= 1) s += __shfl_xor_sync(0xFFFFFFFFu, s, off);
            if (lane == 0) {
                float z = s + blv;
                fout[c] = 1.0f / (1.0f + expf(-z));
            }
        }
    }
}

// ---------------------------------------------------------------------------
extern "C" void kernel_launch(void* const* d_in, const int* in_sizes, int n_in,
                              void* d_out, int out_size) {
    const float* x  = (const float*)d_in[0];
    const int*   ei = (const int*)  d_in[1];
    const float* W1 = (const float*)d_in[2];
    const float* b1 = (const float*)d_in[3];
    const float* W2 = (const float*)d_in[4];
    const float* b2 = (const float*)d_in[5];
    const float* Wl = (const float*)d_in[6];
    const float* bl = (const float*)d_in[7];

    int n = in_sizes[0] / F;
    int E = in_sizes[1] / 2;
    const int* rowp = ei;
    const int* colp = ei + E;

    int *cnt, *start, *cursor, *bsum, *boff, *srow;
    float *dinv;
    uint8_t *h8, *a8;
    h16_t *w1h, *w2h;
    cudaGetSymbolAddress((void**)&cnt,    g_cnt);
    cudaGetSymbolAddress((void**)&start,  g_start);
    cudaGetSymbolAddress((void**)&cursor, g_cursor);
    cudaGetSymbolAddress((void**)&bsum,   g_bsum);
    cudaGetSymbolAddress((void**)&boff,   g_boff);
    cudaGetSymbolAddress((void**)&srow,   g_srow);
    cudaGetSymbolAddress((void**)&dinv,   g_dinv);
    cudaGetSymbolAddress((void**)&h8,     g_h8);
    cudaGetSymbolAddress((void**)&a8,     g_a8);
    cudaGetSymbolAddress((void**)&w1h,    g_w1h);
    cudaGetSymbolAddress((void**)&w2h,    g_w2h);

    const size_t gemm_smem = (size_t)(2 * 128 * SLD) * sizeof(h16_t);
    cudaFuncSetAttribute((const void*)k_gemm_mma<float>,
                         cudaFuncAttributeMaxDynamicSharedMemorySize, (int)gemm_smem);
    cudaFuncSetAttribute((const void*)k_gemm_mma<uint8_t>,
                         cudaFuncAttributeMaxDynamicSharedMemorySize, (int)gemm_smem);

    // Side stream + events for overlapping prep with GEMM1.
    static cudaStream_t s2 = nullptr;
    static cudaEvent_t evF = nullptr, evA = nullptr, evB = nullptr, evW = nullptr;
    static int init_tried = 0;
    if (!init_tried) {
        init_tried = 1;
        if (cudaStreamCreateWithFlags(&s2, cudaStreamNonBlocking) != cudaSuccess) s2 = nullptr;
        if (cudaEventCreateWithFlags(&evF, cudaEventDisableTiming) != cudaSuccess) evF = nullptr;
        if (cudaEventCreateWithFlags(&evA, cudaEventDisableTiming) != cudaSuccess) evA = nullptr;
        if (cudaEventCreateWithFlags(&evB, cudaEventDisableTiming) != cudaSuccess) evB = nullptr;
        if (cudaEventCreateWithFlags(&evW, cudaEventDisableTiming) != cudaSuccess) evW = nullptr;
    }
    bool par = (s2 != nullptr) && (evF != nullptr) && (evA != nullptr) &&
               (evB != nullptr) && (evW != nullptr);

    int nb = (n + SCAN_BLK - 1) / SCAN_BLK;
    int gemm_grid = (n + 127) / 128;
    int agg_grid  = ((n + NPW - 1) / NPW * 32 + 255) / 256;

    cudaMemsetAsync(cnt, 0, (size_t)n * sizeof(int), 0);

    if (par) {
        // Fork s2 immediately (after memset node) — convw has no data deps.
        cudaEventRecord(evF, 0);
        cudaStreamWaitEvent(s2, evF, 0);
        k_convw<<<16, 256, 0, s2>>>(W1, W2, w1h, w2h);   // runs at t~0, concurrent with hist
        cudaEventRecord(evW, s2);

        // stream 0: degree + dinv
        k_hist<<<(E + 255) / 256, 256>>>(colp, cnt, E);
        k_dinv<<<(n + 255) / 256, 256>>>(cnt, dinv, n);
        cudaEventRecord(evA, 0);                          // cnt+dinv done

        // stream 0: GEMM1 (needs dinv + w1h; evW long satisfied by now)
        cudaStreamWaitEvent(0, evW, 0);
        k_gemm_mma<float><<<gemm_grid, 512, gemm_smem>>>(x, w1h, dinv, h8, FP8_SCALE, n);

        // s2: sort chain (needs cnt), concurrent with GEMM1
        cudaStreamWaitEvent(s2, evA, 0);
        k_blocksum  <<<nb, 256, 0, s2>>>(cnt, bsum, n);
        k_scanbsum  <<<1, 256, 0, s2>>>(bsum, boff, start, nb, n);
        k_writestart<<<nb, 256, 0, s2>>>(cnt, boff, start, cursor, n);
        k_scatter   <<<(E + 255) / 256, 256, 0, s2>>>(rowp, colp, cursor, srow, E);
        cudaEventRecord(evB, s2);
        cudaStreamWaitEvent(0, evB, 0);
    } else {
        k_convw<<<16, 256>>>(W1, W2, w1h, w2h);
        k_hist<<<(E + 255) / 256, 256>>>(colp, cnt, E);
        k_dinv<<<(n + 255) / 256, 256>>>(cnt, dinv, n);
        k_gemm_mma<float><<<gemm_grid, 512, gemm_smem>>>(x, w1h, dinv, h8, FP8_SCALE, n);
        k_blocksum  <<<nb, 256>>>(cnt, bsum, n);
        k_scanbsum  <<<1, 256>>>(bsum, boff, start, nb, n);
        k_writestart<<<nb, 256>>>(cnt, boff, start, cursor, n);
        k_scatter   <<<(E + 255) / 256, 256>>>(rowp, colp, cursor, srow, E);
    }

    // --- layer 1 agg (fp8 gather) -> fp8 a8 (x16) ---
    k_agg<false><<<agg_grid, 256>>>(start, srow, dinv, h8, b1, nullptr, nullptr, a8, nullptr, n);

    // --- layer 2: A carries x16 -> esc = 1.0 keeps H8 = 16*dinv*(a@W2) ---
    k_gemm_mma<uint8_t><<<gemm_grid, 512, gemm_smem>>>(a8, w2h, dinv, h8, 1.0f, n);
    k_agg<true><<<agg_grid, 256>>>(start, srow, dinv, h8, b2, Wl, bl, nullptr, (float*)d_out, n);
}